// round 4
// baseline (speedup 1.0000x reference)
#include <cuda_runtime.h>
#include <cuda_bf16.h>
#include <cstdint>

#define BB    8192
#define NVV   778
#define NJJ   16
#define CTOT  2334
#define CPAD  2496          // 13 * 192
#define GK    192           // padded K (145 feat + 1 bias + pad)

// ---------------- device scratch (static; no runtime alloc) ----------------
__device__ __align__(16) __nv_bfloat16  g_Ahi[BB * GK];
__device__ __align__(16) __nv_bfloat16  g_Alo[BB * GK];
__device__ __align__(16) __nv_bfloat16  g_Bhi[CPAD * GK];            // B^T [n][k]
__device__ __align__(16) __nv_bfloat16  g_Blo[CPAD * GK];
__device__ __align__(16) float g_J0[NJJ * 3];
__device__ __align__(16) float g_JS[NJJ * 3 * 10];
// M'' batch-pair interleaved: [b/2][j][k][parity]
__device__ __align__(16) float g_M[(BB / 2) * NJJ * 12 * 2];

__constant__ int c_par[16] = {0,0,1,2,0,4,5,0,7,8,0,10,11,0,13,14};
__constant__ int c_inv[16] = {0,5,6,7,9,10,11,17,18,19,13,14,15,1,2,3};

// ---------------- helpers ----------------
__device__ __forceinline__ void split_bf16(float v, __nv_bfloat16& hi,
                                           __nv_bfloat16& lo) {
    hi = __float2bfloat16_rn(v);
    lo = __float2bfloat16_rn(v - __bfloat162float(hi));
}

typedef unsigned long long ull;

__device__ __forceinline__ ull pk2(float lo, float hi) {
    ull r;
    asm("mov.b64 %0, {%1, %2};" : "=l"(r) : "f"(lo), "f"(hi));
    return r;
}
__device__ __forceinline__ void upk2(ull v, float& lo, float& hi) {
    asm("mov.b64 {%0, %1}, %2;" : "=f"(lo), "=f"(hi) : "l"(v));
}
__device__ __forceinline__ ull f2fma(ull a, ull b, ull c) {
    ull d;
    asm("fma.rn.f32x2 %0, %1, %2, %3;" : "=l"(d) : "l"(a), "l"(b), "l"(c));
    return d;
}

__device__ __forceinline__ void mma16816(float* d, const uint32_t* a,
                                         const uint32_t* b) {
    asm volatile(
        "mma.sync.aligned.m16n8k16.row.col.f32.bf16.bf16.f32 "
        "{%0,%1,%2,%3}, {%4,%5,%6,%7}, {%8,%9}, {%0,%1,%2,%3};"
        : "+f"(d[0]), "+f"(d[1]), "+f"(d[2]), "+f"(d[3])
        : "r"(a[0]), "r"(a[1]), "r"(a[2]), "r"(a[3]), "r"(b[0]), "r"(b[1]));
}

__device__ __forceinline__ uint32_t smem_u32(const void* p) {
    uint32_t a;
    asm("{ .reg .u64 t; cvta.to.shared.u64 t, %1; cvt.u32.u64 %0, t; }"
        : "=r"(a) : "l"(p));
    return a;
}
__device__ __forceinline__ void cpasync16(uint32_t dst, const void* src) {
    asm volatile("cp.async.ca.shared.global [%0], [%1], 16;"
                 :: "r"(dst), "l"(src));
}
#define CP_COMMIT()  asm volatile("cp.async.commit_group;" ::: "memory")
#define CP_WAIT(n)   asm volatile("cp.async.wait_group %0;" :: "n"(n) : "memory")

// ---------------------------------------------------------------------------
// K0B: build B^T hi/lo [n][k]  — coalesced pd reads (n fastest per thread)
// ---------------------------------------------------------------------------
__global__ void k0_B(const float* __restrict__ vt,
                     const float* __restrict__ sd,
                     const float* __restrict__ pd) {
    int n = blockIdx.x * blockDim.x + threadIdx.x;
    int kg = blockIdx.y;
    if (n >= CPAD) return;

    unsigned short hs[8], ls[8];
#pragma unroll
    for (int i = 0; i < 8; i++) {
        int k = kg * 8 + i;
        float val = 0.f;
        if (n < CTOT) {
            if (k < 10)        val = sd[n * 10 + k];
            else if (k < 145)  val = pd[(k - 10) * CTOT + n];
            else if (k == 145) val = vt[n];
        }
        __nv_bfloat16 hi, lo;
        split_bf16(val, hi, lo);
        hs[i] = __bfloat16_as_ushort(hi);
        ls[i] = __bfloat16_as_ushort(lo);
    }
    uint4 ph, pl;
    ph.x = hs[0] | ((uint32_t)hs[1] << 16); ph.y = hs[2] | ((uint32_t)hs[3] << 16);
    ph.z = hs[4] | ((uint32_t)hs[5] << 16); ph.w = hs[6] | ((uint32_t)hs[7] << 16);
    pl.x = ls[0] | ((uint32_t)ls[1] << 16); pl.y = ls[2] | ((uint32_t)ls[3] << 16);
    pl.z = ls[4] | ((uint32_t)ls[5] << 16); pl.w = ls[6] | ((uint32_t)ls[7] << 16);
    *reinterpret_cast<uint4*>(&g_Bhi[n * GK + kg * 8]) = ph;
    *reinterpret_cast<uint4*>(&g_Blo[n * GK + kg * 8]) = pl;
}

// ---------------------------------------------------------------------------
// K0A: feat hi/lo bf16 [B x 192]
// ---------------------------------------------------------------------------
__global__ void k0_A(const float* __restrict__ shape,
                     const float* __restrict__ finger) {
    int idx = blockIdx.x * blockDim.x + threadIdx.x;
    if (idx >= BB * GK) return;
    int b = idx / GK, k = idx - b * GK;
    float val = 0.f;
    if (k < 10) val = shape[b * 10 + k];
    else if (k < 145) {
        int q = k - 10;
        val = finger[b * 135 + q];
        if (((q % 9) & 3) == 0) val -= 1.0f;
    } else if (k == 145) val = 1.0f;
    __nv_bfloat16 hi, lo;
    split_bf16(val, hi, lo);
    g_Ahi[idx] = hi;
    g_Alo[idx] = lo;
}

// ---------------------------------------------------------------------------
// K1: joint regressor contractions
// ---------------------------------------------------------------------------
__global__ void k1_jreg(const float* __restrict__ jreg,
                        const float* __restrict__ vt,
                        const float* __restrict__ sd) {
    __shared__ float red[33 * 128];
    const int j = blockIdx.x, tid = threadIdx.x;
    float acc[33];
#pragma unroll
    for (int o = 0; o < 33; o++) acc[o] = 0.f;
    for (int v = tid; v < NVV; v += 128) {
        float w = jreg[j * NVV + v];
#pragma unroll
        for (int k = 0; k < 3; k++) {
            acc[k] += w * vt[v * 3 + k];
#pragma unroll
            for (int l = 0; l < 10; l++)
                acc[3 + k * 10 + l] += w * sd[(v * 3 + k) * 10 + l];
        }
    }
    for (int o = 0; o < 33; o++) red[o * 128 + tid] = acc[o];
    __syncthreads();
    if (tid < 33) {
        float s = 0.f;
        for (int i = 0; i < 128; i++) s += red[tid * 128 + i];
        if (tid < 3) g_J0[j * 3 + tid] = s;
        else {
            int o = tid - 3;
            int k = o / 10, l = o - k * 10;
            g_JS[(j * 3 + k) * 10 + l] = s;
        }
    }
}

// ---------------------------------------------------------------------------
// K2: per-batch joint chain, M'' (pair-interleaved), 16 regular joints
// ---------------------------------------------------------------------------
__device__ __forceinline__ void mul4(const float* a, float* d) {
    float t[16];
#pragma unroll
    for (int r = 0; r < 4; r++)
#pragma unroll
        for (int c = 0; c < 4; c++)
            t[r * 4 + c] = a[r * 4 + 0] * d[0 + c] + a[r * 4 + 1] * d[4 + c] +
                           a[r * 4 + 2] * d[8 + c] + a[r * 4 + 3] * d[12 + c];
#pragma unroll
    for (int i = 0; i < 16; i++) d[i] = t[i];
}

__global__ void k2_joints(const float* __restrict__ grmt,
                          const float* __restrict__ frmt,
                          const float* __restrict__ shape,
                          const float* __restrict__ trans,
                          float* __restrict__ outJ) {
    __shared__ float sJ[16][3];
    __shared__ float sM[16][16];
    __shared__ float sg[9], st[3], ssh[10];
    const int b = blockIdx.x, tid = threadIdx.x;

    if (tid < 9)  sg[tid]  = grmt[b * 9 + tid];
    if (tid < 3)  st[tid]  = trans[b * 3 + tid];
    if (tid < 10) ssh[tid] = shape[b * 10 + tid];
    __syncthreads();

    if (tid < 48) {
        int j = tid / 3, k = tid - j * 3;
        float a = g_J0[j * 3 + k];
#pragma unroll
        for (int l = 0; l < 10; l++) a += ssh[l] * g_JS[(j * 3 + k) * 10 + l];
        sJ[j][k] = a;
    }
    __syncthreads();

    if (tid < 16) {
        int j = tid;
        float R[9];
        if (j == 0) {
            R[0]=1;R[1]=0;R[2]=0;R[3]=0;R[4]=1;R[5]=0;R[6]=0;R[7]=0;R[8]=1;
        } else {
#pragma unroll
            for (int i = 0; i < 9; i++) R[i] = frmt[b * 135 + (j - 1) * 9 + i];
        }
        float t0 = sJ[j][0], t1 = sJ[j][1], t2 = sJ[j][2];
        if (j > 0) {
            int p = c_par[j];
            t0 -= sJ[p][0]; t1 -= sJ[p][1]; t2 -= sJ[p][2];
        }
        float* m = sM[j];
        m[0]=R[0]; m[1]=R[1]; m[2]=R[2];  m[3]=t0;
        m[4]=R[3]; m[5]=R[4]; m[6]=R[5];  m[7]=t1;
        m[8]=R[6]; m[9]=R[7]; m[10]=R[8]; m[11]=t2;
        m[12]=0.f; m[13]=0.f; m[14]=0.f;  m[15]=1.f;
    }
    __syncthreads();

    if (tid < 5) {
        int j = 1 + 3 * tid;
        mul4(sM[0], sM[j]);
        mul4(sM[j], sM[j + 1]);
        mul4(sM[j + 1], sM[j + 2]);
    }
    __syncthreads();

    if (tid < 16) {
        int j = tid;
        const float* m = sM[j];
        float jt0 = m[3], jt1 = m[7], jt2 = m[11];
        float J0 = sJ[j][0], J1 = sJ[j][1], J2 = sJ[j][2];
        float tc0 = jt0 - (m[0] * J0 + m[1] * J1 + m[2]  * J2);
        float tc1 = jt1 - (m[4] * J0 + m[5] * J1 + m[6]  * J2);
        float tc2 = jt2 - (m[8] * J0 + m[9] * J1 + m[10] * J2);
        float* o = &g_M[(((b >> 1) * 16 + j) * 12) * 2 + (b & 1)];
        float row[12];
        int jp = c_inv[j];
#pragma unroll
        for (int r = 0; r < 3; r++) {
            float a = sg[r * 3 + 0], bb = sg[r * 3 + 1], cc = sg[r * 3 + 2];
            row[r * 4 + 0] = a * m[0] + bb * m[4] + cc * m[8];
            row[r * 4 + 1] = a * m[1] + bb * m[5] + cc * m[9];
            row[r * 4 + 2] = a * m[2] + bb * m[6] + cc * m[10];
            row[r * 4 + 3] = a * tc0  + bb * tc1  + cc * tc2 + st[r];
            outJ[(b * 21 + jp) * 3 + r] = a * jt0 + bb * jt1 + cc * jt2 + st[r];
        }
#pragma unroll
        for (int k = 0; k < 12; k++) o[k * 2] = row[k];
    }
}

// ---------------------------------------------------------------------------
// K3: FUSED mma.sync GEMM (cp.async 2-stage) + f32x2 LBS epilogue.
//   CTA: 512 thr, tile 128(b) x 192(n) = 64 verts. grid (64, 13)
//   Stage layout (92160 B each, 2 stages):
//     A_hi 0..18432, A_lo ..36864, B_hi ..64512, B_lo ..92160
//   Epilogue reuse: sV (128 x 204 f) @0, sM (64 x 392 f) @104448, sW @204800
// ---------------------------------------------------------------------------
#define STG_SZ   92160
#define EP_SV    0
#define EP_SM    104448
#define EP_SW    204800
#define SM_FUSE  212992
#define SVSTR    204

__global__ __launch_bounds__(512, 1) void k3_fused(const float* __restrict__ lbs,
                                                   float* __restrict__ outV,
                                                   float* __restrict__ outJ) {
    extern __shared__ __align__(16) char smem[];
    const uint32_t sbase = smem_u32(smem);
    const int tid = threadIdx.x;
    const int wid = tid >> 5, lane = tid & 31;
    const int wm = wid & 1, wn = wid >> 1;      // 2 m-warps x 8 n-warps
    const int gid = lane >> 2, tig = lane & 3;
    const int b0 = blockIdx.x * 128;
    const int t  = blockIdx.y;

    // ---- async stage of one K-chunk into stage s ----
    auto stage_chunk = [&](int s, int ch) {
        const uint32_t stg = sbase + s * STG_SZ;
        for (int i = tid; i < 5120; i += 512) {
            if (i < 2048) {
                int split = i >> 10, r = (i >> 3) & 127, q = i & 7;
                const __nv_bfloat16* src = split ? g_Alo : g_Ahi;
                cpasync16(stg + split * 18432 + r * 144 + q * 16,
                          &src[(b0 + r) * GK + ch * 64 + q * 8]);
            } else {
                int i2 = i - 2048;
                int split = i2 / 1536, rem = i2 - split * 1536;
                int r = rem >> 3, q = rem & 7;
                const __nv_bfloat16* src = split ? g_Blo : g_Bhi;
                cpasync16(stg + 36864 + split * 27648 + r * 144 + q * 16,
                          &src[(t * 192 + r) * GK + ch * 64 + q * 8]);
            }
        }
    };

    float d[4][3][4];
#pragma unroll
    for (int mt = 0; mt < 4; mt++)
#pragma unroll
        for (int nt = 0; nt < 3; nt++)
#pragma unroll
            for (int q = 0; q < 4; q++) d[mt][nt][q] = 0.f;

    stage_chunk(0, 0); CP_COMMIT();
    stage_chunk(1, 1); CP_COMMIT();

    auto mma_chunk = [&](int s) {
        const char* stg = smem + s * STG_SZ;
#pragma unroll
        for (int ks = 0; ks < 4; ks++) {
            const int kb = ks * 32 + tig * 4;
            uint32_t ah[4][4], al[4][4];
#pragma unroll
            for (int mt = 0; mt < 4; mt++) {
                int r0 = wm * 64 + mt * 16 + gid;
                const char* ph = stg + r0 * 144 + kb;
                const char* pl = stg + 18432 + r0 * 144 + kb;
                ah[mt][0] = *(const uint32_t*)(ph);
                ah[mt][1] = *(const uint32_t*)(ph + 8 * 144);
                ah[mt][2] = *(const uint32_t*)(ph + 16);
                ah[mt][3] = *(const uint32_t*)(ph + 8 * 144 + 16);
                al[mt][0] = *(const uint32_t*)(pl);
                al[mt][1] = *(const uint32_t*)(pl + 8 * 144);
                al[mt][2] = *(const uint32_t*)(pl + 16);
                al[mt][3] = *(const uint32_t*)(pl + 8 * 144 + 16);
            }
            uint32_t bh[3][2], bl[3][2];
#pragma unroll
            for (int nt = 0; nt < 3; nt++) {
                int n0 = wn * 24 + nt * 8 + gid;
                const char* ph = stg + 36864 + n0 * 144 + kb;
                const char* pl = stg + 64512 + n0 * 144 + kb;
                bh[nt][0] = *(const uint32_t*)(ph);
                bh[nt][1] = *(const uint32_t*)(ph + 16);
                bl[nt][0] = *(const uint32_t*)(pl);
                bl[nt][1] = *(const uint32_t*)(pl + 16);
            }
#pragma unroll
            for (int mt = 0; mt < 4; mt++)
#pragma unroll
                for (int nt = 0; nt < 3; nt++) {
                    mma16816(d[mt][nt], ah[mt], bh[nt]);
                    mma16816(d[mt][nt], al[mt], bh[nt]);
                    mma16816(d[mt][nt], ah[mt], bl[nt]);
                }
        }
    };

    // ch 0
    CP_WAIT(1); __syncthreads();
    mma_chunk(0);
    __syncthreads();
    stage_chunk(0, 2); CP_COMMIT();
    // ch 1
    CP_WAIT(1); __syncthreads();
    mma_chunk(1);
    // ch 2
    CP_WAIT(0); __syncthreads();
    mma_chunk(0);
    __syncthreads();   // all MMA smem reads done before overwriting stages

    // ---- write V fragments into sV (stride 204, conflict-free) ----
    float* sV = reinterpret_cast<float*>(smem + EP_SV);
    float* sM = reinterpret_cast<float*>(smem + EP_SM);
    float* sW = reinterpret_cast<float*>(smem + EP_SW);
#pragma unroll
    for (int mt = 0; mt < 4; mt++) {
        int r0 = wm * 64 + mt * 16 + gid;
#pragma unroll
        for (int nt = 0; nt < 3; nt++) {
            int c = wn * 24 + nt * 8 + tig * 2;
            *reinterpret_cast<float2*>(&sV[r0 * SVSTR + c]) =
                make_float2(d[mt][nt][0], d[mt][nt][1]);
            *reinterpret_cast<float2*>(&sV[(r0 + 8) * SVSTR + c]) =
                make_float2(d[mt][nt][2], d[mt][nt][3]);
        }
    }
    // stage M'' (64 pairs x 384 f, contiguous) and duplicated weights
    {
        const float4* src = reinterpret_cast<const float4*>(
            &g_M[(size_t)(b0 / 2) * 384]);
        for (int i = tid; i < 6144; i += 512) {
            int pr = i / 96, q = i - pr * 96;
            *reinterpret_cast<float4*>(&sM[pr * 392 + q * 4]) = src[i];
        }
    }
    const int v0 = t * 64;
    for (int i = tid; i < 1024; i += 512) {
        int v = i >> 4, j = i & 15;
        float w = (v0 + v < NVV) ? lbs[(v0 + v) * 16 + j] : 0.f;
        sW[(j * 64 + v) * 2]     = w;
        sW[(j * 64 + v) * 2 + 1] = w;
    }
    __syncthreads();

    // ---- epilogue: 2 iterations, thread = (pair, 4 verts) ----
    const int vq = tid & 15;
    const int pq = tid >> 4;            // 0..31

#pragma unroll
    for (int u = 0; u < 2; u++) {
        const int p  = pq + u * 32;     // pair 0..63
        const int bA = b0 + p * 2;

        float va[12], vb[12];
        {
            const float* p0 = &sV[(p * 2) * SVSTR + vq * 12];
            const float* p1 = p0 + SVSTR;
#pragma unroll
            for (int q = 0; q < 3; q++) {
                float4 x0 = reinterpret_cast<const float4*>(p0)[q];
                float4 x1 = reinterpret_cast<const float4*>(p1)[q];
                va[q*4+0]=x0.x; va[q*4+1]=x0.y; va[q*4+2]=x0.z; va[q*4+3]=x0.w;
                vb[q*4+0]=x1.x; vb[q*4+1]=x1.y; vb[q*4+2]=x1.z; vb[q*4+3]=x1.w;
            }
        }
        ull pX[4], pY[4], pZ[4];
#pragma unroll
        for (int vi = 0; vi < 4; vi++) {
            pX[vi] = pk2(va[vi * 3 + 0], vb[vi * 3 + 0]);
            pY[vi] = pk2(va[vi * 3 + 1], vb[vi * 3 + 1]);
            pZ[vi] = pk2(va[vi * 3 + 2], vb[vi * 3 + 2]);
        }

        ull o[12];
#pragma unroll
        for (int i = 0; i < 12; i++) o[i] = 0ull;

#pragma unroll 4
        for (int j = 0; j < 16; j++) {
            const ull* mp = reinterpret_cast<const ull*>(&sM[p * 392 + j * 24]);
            const ull* wp = reinterpret_cast<const ull*>(&sW[(j * 64 + vq * 4) * 2]);
            ull m0 = mp[0], m1 = mp[1], m2 = mp[2],  m3 = mp[3];
            ull m4 = mp[4], m5 = mp[5], m6 = mp[6],  m7 = mp[7];
            ull m8 = mp[8], m9 = mp[9], m10 = mp[10], m11 = mp[11];
#pragma unroll
            for (int vi = 0; vi < 4; vi++) {
                ull w = wp[vi];
                ull t0 = f2fma(m0, pX[vi], f2fma(m1, pY[vi], f2fma(m2,  pZ[vi], m3)));
                ull t1 = f2fma(m4, pX[vi], f2fma(m5, pY[vi], f2fma(m6,  pZ[vi], m7)));
                ull t2 = f2fma(m8, pX[vi], f2fma(m9, pY[vi], f2fma(m10, pZ[vi], m11)));
                o[vi * 3 + 0] = f2fma(w, t0, o[vi * 3 + 0]);
                o[vi * 3 + 1] = f2fma(w, t1, o[vi * 3 + 1]);
                o[vi * 3 + 2] = f2fma(w, t2, o[vi * 3 + 2]);
            }
        }

        float oa[12], ob[12];
#pragma unroll
        for (int i = 0; i < 12; i++) upk2(o[i], oa[i], ob[i]);

        // fingertip joints
#pragma unroll
        for (int vi = 0; vi < 4; vi++) {
            int v = v0 + vq * 4 + vi;
            int tp = -1;
            if (v == 745) tp = 4; else if (v == 317) tp = 8;
            else if (v == 444) tp = 12; else if (v == 556) tp = 16;
            else if (v == 673) tp = 20;
            if (tp >= 0) {
                int base = vi * 3;
                outJ[((bA)     * 21 + tp) * 3 + 0] = oa[base + 0];
                outJ[((bA)     * 21 + tp) * 3 + 1] = oa[base + 1];
                outJ[((bA)     * 21 + tp) * 3 + 2] = oa[base + 2];
                outJ[((bA + 1) * 21 + tp) * 3 + 0] = ob[base + 0];
                outJ[((bA + 1) * 21 + tp) * 3 + 1] = ob[base + 1];
                outJ[((bA + 1) * 21 + tp) * 3 + 2] = ob[base + 2];
            }
        }

        const int cbase = v0 * 3 + vq * 12;
        if (cbase + 12 <= CTOT) {
            float* p0 = &outV[(size_t)bA * CTOT + cbase];
            float* p1 = p0 + CTOT;
#pragma unroll
            for (int q = 0; q < 6; q++) {
                reinterpret_cast<float2*>(p0)[q] = make_float2(oa[q*2], oa[q*2+1]);
                reinterpret_cast<float2*>(p1)[q] = make_float2(ob[q*2], ob[q*2+1]);
            }
        } else if (cbase < CTOT) {
            int nval = CTOT - cbase;
            float* p0 = &outV[(size_t)bA * CTOT + cbase];
            float* p1 = p0 + CTOT;
            for (int q = 0; q < nval; q++) { p0[q] = oa[q]; p1[q] = ob[q]; }
        }
    }
}

// ---------------------------------------------------------------------------
extern "C" void kernel_launch(void* const* d_in, const int* in_sizes, int n_in,
                              void* d_out, int out_size) {
    const float* grmt  = (const float*)d_in[0];
    const float* frmt  = (const float*)d_in[1];
    const float* shape = (const float*)d_in[2];
    const float* trans = (const float*)d_in[3];
    const float* vt    = (const float*)d_in[4];
    const float* sd    = (const float*)d_in[5];
    const float* jreg  = (const float*)d_in[6];
    const float* pd    = (const float*)d_in[7];
    const float* lbs   = (const float*)d_in[8];

    float* out  = (float*)d_out;
    float* outV = out;
    float* outJ = out + (size_t)BB * CTOT;

    static bool attr_done = false;
    if (!attr_done) {
        cudaFuncSetAttribute(k3_fused, cudaFuncAttributeMaxDynamicSharedMemorySize,
                             SM_FUSE);
        attr_done = true;
    }

    k0_B<<<dim3((CPAD + 255) / 256, 24), 256>>>(vt, sd, pd);
    k0_A<<<(BB * GK) / 256, 256>>>(shape, frmt);
    k1_jreg<<<NJJ, 128>>>(jreg, vt, sd);
    k2_joints<<<BB, 64>>>(grmt, frmt, shape, trans, outJ);
    k3_fused<<<dim3(BB / 128, 13), 512, SM_FUSE>>>(lbs, outV, outJ);
}

// round 5
// speedup vs baseline: 1.4858x; 1.4858x over previous
#include <cuda_runtime.h>
#include <cuda_bf16.h>
#include <cstdint>

#define BB    8192
#define NVV   778
#define NJJ   16
#define CTOT  2334
#define CPAD  2496          // 13 * 192
#define GK    192           // padded K (145 feat + 1 bias + pad)

// ---------------- device scratch (static; no runtime alloc) ----------------
__device__ __align__(16) float          g_V[(size_t)BB * CPAD];      // GEMM out
__device__ __align__(16) __nv_bfloat16  g_Ahi[BB * GK];
__device__ __align__(16) __nv_bfloat16  g_Alo[BB * GK];
__device__ __align__(16) __nv_bfloat16  g_Bhi[CPAD * GK];            // B^T [n][k]
__device__ __align__(16) __nv_bfloat16  g_Blo[CPAD * GK];
__device__ __align__(16) float g_J0[NJJ * 3];
__device__ __align__(16) float g_JS[NJJ * 3 * 10];
// M'' batch-pair interleaved: [b/2][j][k][parity]
__device__ __align__(16) float g_M[(BB / 2) * NJJ * 12 * 2];

__constant__ int c_par[16] = {0,0,1,2,0,4,5,0,7,8,0,10,11,0,13,14};
__constant__ int c_inv[16] = {0,5,6,7,9,10,11,17,18,19,13,14,15,1,2,3};

// ---------------- helpers ----------------
__device__ __forceinline__ void split_bf16(float v, __nv_bfloat16& hi,
                                           __nv_bfloat16& lo) {
    hi = __float2bfloat16_rn(v);
    lo = __float2bfloat16_rn(v - __bfloat162float(hi));
}

typedef unsigned long long ull;

__device__ __forceinline__ ull pk2(float lo, float hi) {
    ull r;
    asm("mov.b64 %0, {%1, %2};" : "=l"(r) : "f"(lo), "f"(hi));
    return r;
}
__device__ __forceinline__ void upk2(ull v, float& lo, float& hi) {
    asm("mov.b64 {%0, %1}, %2;" : "=f"(lo), "=f"(hi) : "l"(v));
}
__device__ __forceinline__ ull f2fma(ull a, ull b, ull c) {
    ull d;
    asm("fma.rn.f32x2 %0, %1, %2, %3;" : "=l"(d) : "l"(a), "l"(b), "l"(c));
    return d;
}

__device__ __forceinline__ void mma16816(float* d, const uint32_t* a,
                                         const uint32_t* b) {
    asm volatile(
        "mma.sync.aligned.m16n8k16.row.col.f32.bf16.bf16.f32 "
        "{%0,%1,%2,%3}, {%4,%5,%6,%7}, {%8,%9}, {%0,%1,%2,%3};"
        : "+f"(d[0]), "+f"(d[1]), "+f"(d[2]), "+f"(d[3])
        : "r"(a[0]), "r"(a[1]), "r"(a[2]), "r"(a[3]), "r"(b[0]), "r"(b[1]));
}

__device__ __forceinline__ uint32_t smem_u32(const void* p) {
    uint32_t a;
    asm("{ .reg .u64 t; cvta.to.shared.u64 t, %1; cvt.u32.u64 %0, t; }"
        : "=r"(a) : "l"(p));
    return a;
}
__device__ __forceinline__ void cpasync16(uint32_t dst, const void* src) {
    asm volatile("cp.async.ca.shared.global [%0], [%1], 16;"
                 :: "r"(dst), "l"(src));
}
#define CP_COMMIT()  asm volatile("cp.async.commit_group;" ::: "memory")
#define CP_WAIT(n)   asm volatile("cp.async.wait_group %0;" :: "n"(n) : "memory")

// ---------------------------------------------------------------------------
// K0B: build B^T hi/lo [n][k]  — coalesced pd reads
// ---------------------------------------------------------------------------
__global__ void k0_B(const float* __restrict__ vt,
                     const float* __restrict__ sd,
                     const float* __restrict__ pd) {
    int n = blockIdx.x * blockDim.x + threadIdx.x;
    int kg = blockIdx.y;
    if (n >= CPAD) return;

    unsigned short hs[8], ls[8];
#pragma unroll
    for (int i = 0; i < 8; i++) {
        int k = kg * 8 + i;
        float val = 0.f;
        if (n < CTOT) {
            if (k < 10)        val = sd[n * 10 + k];
            else if (k < 145)  val = pd[(k - 10) * CTOT + n];
            else if (k == 145) val = vt[n];
        }
        __nv_bfloat16 hi, lo;
        split_bf16(val, hi, lo);
        hs[i] = __bfloat16_as_ushort(hi);
        ls[i] = __bfloat16_as_ushort(lo);
    }
    uint4 ph, pl;
    ph.x = hs[0] | ((uint32_t)hs[1] << 16); ph.y = hs[2] | ((uint32_t)hs[3] << 16);
    ph.z = hs[4] | ((uint32_t)hs[5] << 16); ph.w = hs[6] | ((uint32_t)hs[7] << 16);
    pl.x = ls[0] | ((uint32_t)ls[1] << 16); pl.y = ls[2] | ((uint32_t)ls[3] << 16);
    pl.z = ls[4] | ((uint32_t)ls[5] << 16); pl.w = ls[6] | ((uint32_t)ls[7] << 16);
    *reinterpret_cast<uint4*>(&g_Bhi[n * GK + kg * 8]) = ph;
    *reinterpret_cast<uint4*>(&g_Blo[n * GK + kg * 8]) = pl;
}

// ---------------------------------------------------------------------------
// K0A: feat hi/lo bf16 [B x 192]
// ---------------------------------------------------------------------------
__global__ void k0_A(const float* __restrict__ shape,
                     const float* __restrict__ finger) {
    int idx = blockIdx.x * blockDim.x + threadIdx.x;
    if (idx >= BB * GK) return;
    int b = idx / GK, k = idx - b * GK;
    float val = 0.f;
    if (k < 10) val = shape[b * 10 + k];
    else if (k < 145) {
        int q = k - 10;
        val = finger[b * 135 + q];
        if (((q % 9) & 3) == 0) val -= 1.0f;
    } else if (k == 145) val = 1.0f;
    __nv_bfloat16 hi, lo;
    split_bf16(val, hi, lo);
    g_Ahi[idx] = hi;
    g_Alo[idx] = lo;
}

// ---------------------------------------------------------------------------
// K1: joint regressor contractions
// ---------------------------------------------------------------------------
__global__ void k1_jreg(const float* __restrict__ jreg,
                        const float* __restrict__ vt,
                        const float* __restrict__ sd) {
    __shared__ float red[33 * 128];
    const int j = blockIdx.x, tid = threadIdx.x;
    float acc[33];
#pragma unroll
    for (int o = 0; o < 33; o++) acc[o] = 0.f;
    for (int v = tid; v < NVV; v += 128) {
        float w = jreg[j * NVV + v];
#pragma unroll
        for (int k = 0; k < 3; k++) {
            acc[k] += w * vt[v * 3 + k];
#pragma unroll
            for (int l = 0; l < 10; l++)
                acc[3 + k * 10 + l] += w * sd[(v * 3 + k) * 10 + l];
        }
    }
    for (int o = 0; o < 33; o++) red[o * 128 + tid] = acc[o];
    __syncthreads();
    if (tid < 33) {
        float s = 0.f;
        for (int i = 0; i < 128; i++) s += red[tid * 128 + i];
        if (tid < 3) g_J0[j * 3 + tid] = s;
        else {
            int o = tid - 3;
            int k = o / 10, l = o - k * 10;
            g_JS[(j * 3 + k) * 10 + l] = s;
        }
    }
}

// ---------------------------------------------------------------------------
// K2: joint chain — 4 batches per 256-thread CTA
// ---------------------------------------------------------------------------
__device__ __forceinline__ void mul4(const float* a, float* d) {
    float t[16];
#pragma unroll
    for (int r = 0; r < 4; r++)
#pragma unroll
        for (int c = 0; c < 4; c++)
            t[r * 4 + c] = a[r * 4 + 0] * d[0 + c] + a[r * 4 + 1] * d[4 + c] +
                           a[r * 4 + 2] * d[8 + c] + a[r * 4 + 3] * d[12 + c];
#pragma unroll
    for (int i = 0; i < 16; i++) d[i] = t[i];
}

__global__ __launch_bounds__(256) void k2_joints(const float* __restrict__ grmt,
                          const float* __restrict__ frmt,
                          const float* __restrict__ shape,
                          const float* __restrict__ trans,
                          float* __restrict__ outJ) {
    __shared__ float sJ[4][16][3];
    __shared__ float sM[4][16][16];
    __shared__ float sg[4][9], st[4][3], ssh[4][10];
    const int tid = threadIdx.x;
    const int bs = tid >> 6;          // 0..3 batch slot
    const int tl = tid & 63;
    const int b = blockIdx.x * 4 + bs;

    if (tl < 9)  sg[bs][tl]  = grmt[b * 9 + tl];
    if (tl < 3)  st[bs][tl]  = trans[b * 3 + tl];
    if (tl < 10) ssh[bs][tl] = shape[b * 10 + tl];
    __syncthreads();

    if (tl < 48) {
        int j = tl / 3, k = tl - j * 3;
        float a = g_J0[j * 3 + k];
#pragma unroll
        for (int l = 0; l < 10; l++) a += ssh[bs][l] * g_JS[(j * 3 + k) * 10 + l];
        sJ[bs][j][k] = a;
    }
    __syncthreads();

    if (tl < 16) {
        int j = tl;
        float R[9];
        if (j == 0) {
            R[0]=1;R[1]=0;R[2]=0;R[3]=0;R[4]=1;R[5]=0;R[6]=0;R[7]=0;R[8]=1;
        } else {
#pragma unroll
            for (int i = 0; i < 9; i++) R[i] = frmt[b * 135 + (j - 1) * 9 + i];
        }
        float t0 = sJ[bs][j][0], t1 = sJ[bs][j][1], t2 = sJ[bs][j][2];
        if (j > 0) {
            int p = c_par[j];
            t0 -= sJ[bs][p][0]; t1 -= sJ[bs][p][1]; t2 -= sJ[bs][p][2];
        }
        float* m = sM[bs][j];
        m[0]=R[0]; m[1]=R[1]; m[2]=R[2];  m[3]=t0;
        m[4]=R[3]; m[5]=R[4]; m[6]=R[5];  m[7]=t1;
        m[8]=R[6]; m[9]=R[7]; m[10]=R[8]; m[11]=t2;
        m[12]=0.f; m[13]=0.f; m[14]=0.f;  m[15]=1.f;
    }
    __syncthreads();

    if (tl < 5) {
        int j = 1 + 3 * tl;
        mul4(sM[bs][0], sM[bs][j]);
        mul4(sM[bs][j], sM[bs][j + 1]);
        mul4(sM[bs][j + 1], sM[bs][j + 2]);
    }
    __syncthreads();

    if (tl < 16) {
        int j = tl;
        const float* m = sM[bs][j];
        float jt0 = m[3], jt1 = m[7], jt2 = m[11];
        float J0 = sJ[bs][j][0], J1 = sJ[bs][j][1], J2 = sJ[bs][j][2];
        float tc0 = jt0 - (m[0] * J0 + m[1] * J1 + m[2]  * J2);
        float tc1 = jt1 - (m[4] * J0 + m[5] * J1 + m[6]  * J2);
        float tc2 = jt2 - (m[8] * J0 + m[9] * J1 + m[10] * J2);
        float* o = &g_M[(((b >> 1) * 16 + j) * 12) * 2 + (b & 1)];
        float row[12];
        int jp = c_inv[j];
#pragma unroll
        for (int r = 0; r < 3; r++) {
            float a = sg[bs][r * 3 + 0], bb = sg[bs][r * 3 + 1], cc = sg[bs][r * 3 + 2];
            row[r * 4 + 0] = a * m[0] + bb * m[4] + cc * m[8];
            row[r * 4 + 1] = a * m[1] + bb * m[5] + cc * m[9];
            row[r * 4 + 2] = a * m[2] + bb * m[6] + cc * m[10];
            row[r * 4 + 3] = a * tc0  + bb * tc1  + cc * tc2 + st[bs][r];
            outJ[(b * 21 + jp) * 3 + r] = a * jt0 + bb * jt1 + cc * jt2 + st[bs][r];
        }
#pragma unroll
        for (int k = 0; k < 12; k++) o[k * 2] = row[k];
    }
}

// ---------------------------------------------------------------------------
// K3: mma.sync bf16-split GEMM with cp.async 2-stage pipeline -> g_V
//   CTA: 512 thr, tile 128(b) x 192(n), K=192 in 3 chunks of 64
// ---------------------------------------------------------------------------
#define STG_SZ  92160
#define SM_K3   184320

__global__ __launch_bounds__(512, 1) void k3_gemm() {
    extern __shared__ __align__(16) char smem[];
    const uint32_t sbase = smem_u32(smem);
    const int tid = threadIdx.x;
    const int wid = tid >> 5, lane = tid & 31;
    const int wm = wid & 1, wn = wid >> 1;      // 2 m-warps x 8 n-warps
    const int gid = lane >> 2, tig = lane & 3;
    const int b0 = blockIdx.x * 128;
    const int t  = blockIdx.y;

    auto stage_chunk = [&](int s, int ch) {
        const uint32_t stg = sbase + s * STG_SZ;
        for (int i = tid; i < 5120; i += 512) {
            if (i < 2048) {
                int split = i >> 10, r = (i >> 3) & 127, q = i & 7;
                const __nv_bfloat16* src = split ? g_Alo : g_Ahi;
                cpasync16(stg + split * 18432 + r * 144 + q * 16,
                          &src[(b0 + r) * GK + ch * 64 + q * 8]);
            } else {
                int i2 = i - 2048;
                int split = i2 / 1536, rem = i2 - split * 1536;
                int r = rem >> 3, q = rem & 7;
                const __nv_bfloat16* src = split ? g_Blo : g_Bhi;
                cpasync16(stg + 36864 + split * 27648 + r * 144 + q * 16,
                          &src[(t * 192 + r) * GK + ch * 64 + q * 8]);
            }
        }
    };

    float d[4][3][4];
#pragma unroll
    for (int mt = 0; mt < 4; mt++)
#pragma unroll
        for (int nt = 0; nt < 3; nt++)
#pragma unroll
            for (int q = 0; q < 4; q++) d[mt][nt][q] = 0.f;

    stage_chunk(0, 0); CP_COMMIT();
    stage_chunk(1, 1); CP_COMMIT();

    auto mma_chunk = [&](int s) {
        const char* stg = smem + s * STG_SZ;
#pragma unroll
        for (int ks = 0; ks < 4; ks++) {
            const int kb = ks * 32 + tig * 4;
            uint32_t ah[4][4], al[4][4];
#pragma unroll
            for (int mt = 0; mt < 4; mt++) {
                int r0 = wm * 64 + mt * 16 + gid;
                const char* ph = stg + r0 * 144 + kb;
                const char* pl = stg + 18432 + r0 * 144 + kb;
                ah[mt][0] = *(const uint32_t*)(ph);
                ah[mt][1] = *(const uint32_t*)(ph + 8 * 144);
                ah[mt][2] = *(const uint32_t*)(ph + 16);
                ah[mt][3] = *(const uint32_t*)(ph + 8 * 144 + 16);
                al[mt][0] = *(const uint32_t*)(pl);
                al[mt][1] = *(const uint32_t*)(pl + 8 * 144);
                al[mt][2] = *(const uint32_t*)(pl + 16);
                al[mt][3] = *(const uint32_t*)(pl + 8 * 144 + 16);
            }
            uint32_t bh[3][2], bl[3][2];
#pragma unroll
            for (int nt = 0; nt < 3; nt++) {
                int n0 = wn * 24 + nt * 8 + gid;
                const char* ph = stg + 36864 + n0 * 144 + kb;
                const char* pl = stg + 64512 + n0 * 144 + kb;
                bh[nt][0] = *(const uint32_t*)(ph);
                bh[nt][1] = *(const uint32_t*)(ph + 16);
                bl[nt][0] = *(const uint32_t*)(pl);
                bl[nt][1] = *(const uint32_t*)(pl + 16);
            }
#pragma unroll
            for (int mt = 0; mt < 4; mt++)
#pragma unroll
                for (int nt = 0; nt < 3; nt++) {
                    mma16816(d[mt][nt], ah[mt], bh[nt]);
                    mma16816(d[mt][nt], al[mt], bh[nt]);
                    mma16816(d[mt][nt], ah[mt], bl[nt]);
                }
        }
    };

    CP_WAIT(1); __syncthreads();
    mma_chunk(0);
    __syncthreads();
    stage_chunk(0, 2); CP_COMMIT();
    CP_WAIT(1); __syncthreads();
    mma_chunk(1);
    CP_WAIT(0); __syncthreads();
    mma_chunk(0);

    // writeout to g_V
#pragma unroll
    for (int mt = 0; mt < 4; mt++) {
        int r0 = b0 + wm * 64 + mt * 16 + gid;
#pragma unroll
        for (int nt = 0; nt < 3; nt++) {
            int c = t * 192 + wn * 24 + nt * 8 + tig * 2;
            *reinterpret_cast<float2*>(&g_V[(size_t)r0 * CPAD + c]) =
                make_float2(d[mt][nt][0], d[mt][nt][1]);
            *reinterpret_cast<float2*>(&g_V[(size_t)(r0 + 8) * CPAD + c]) =
                make_float2(d[mt][nt][2], d[mt][nt][3]);
        }
    }
}

// ---------------------------------------------------------------------------
// K4: LBS epilogue, f32x2-packed over batch pairs (unchanged from R3)
// ---------------------------------------------------------------------------
__global__ __launch_bounds__(256, 2) void k4_epi(const float* __restrict__ lbs,
                                                 float* __restrict__ outV,
                                                 float* __restrict__ outJ) {
    __shared__ __align__(16) float sMmP[16 * 392];
    __shared__ __align__(16) float sW2[16 * 64 * 2];
    const int tid = threadIdx.x;
    const int b0 = blockIdx.x * 32;
    const int v0 = blockIdx.y * 64;
    const int c0 = v0 * 3;

    {
        const float4* src = reinterpret_cast<const float4*>(
            &g_M[(size_t)(b0 / 2) * 384]);
        for (int i = tid; i < 1536; i += 256) {
            int pr = i / 96, q = i - pr * 96;
            *reinterpret_cast<float4*>(&sMmP[pr * 392 + q * 4]) = src[i];
        }
    }
    for (int i = tid; i < 1024; i += 256) {
        int v = i >> 4, j = i & 15;
        float w = (v0 + v < NVV) ? lbs[(v0 + v) * 16 + j] : 0.f;
        sW2[(j * 64 + v) * 2]     = w;
        sW2[(j * 64 + v) * 2 + 1] = w;
    }
    __syncthreads();

    const int vq = tid & 15;
    const int bq = tid >> 4;
    const int bA = b0 + bq * 2;

    float va[12], vb[12];
    {
        const float* p0 = &g_V[(size_t)bA * CPAD + c0 + vq * 12];
        const float* p1 = p0 + CPAD;
#pragma unroll
        for (int q = 0; q < 3; q++) {
            float4 x0 = reinterpret_cast<const float4*>(p0)[q];
            float4 x1 = reinterpret_cast<const float4*>(p1)[q];
            va[q*4+0]=x0.x; va[q*4+1]=x0.y; va[q*4+2]=x0.z; va[q*4+3]=x0.w;
            vb[q*4+0]=x1.x; vb[q*4+1]=x1.y; vb[q*4+2]=x1.z; vb[q*4+3]=x1.w;
        }
    }
    ull pX[4], pY[4], pZ[4];
#pragma unroll
    for (int vi = 0; vi < 4; vi++) {
        pX[vi] = pk2(va[vi * 3 + 0], vb[vi * 3 + 0]);
        pY[vi] = pk2(va[vi * 3 + 1], vb[vi * 3 + 1]);
        pZ[vi] = pk2(va[vi * 3 + 2], vb[vi * 3 + 2]);
    }

    ull o[12];
#pragma unroll
    for (int i = 0; i < 12; i++) o[i] = 0ull;

#pragma unroll 4
    for (int j = 0; j < 16; j++) {
        const ull* mp = reinterpret_cast<const ull*>(&sMmP[bq * 392 + j * 24]);
        const ull* wp = reinterpret_cast<const ull*>(&sW2[(j * 64 + vq * 4) * 2]);
        ull m0 = mp[0], m1 = mp[1], m2 = mp[2],  m3 = mp[3];
        ull m4 = mp[4], m5 = mp[5], m6 = mp[6],  m7 = mp[7];
        ull m8 = mp[8], m9 = mp[9], m10 = mp[10], m11 = mp[11];
#pragma unroll
        for (int vi = 0; vi < 4; vi++) {
            ull w = wp[vi];
            ull t0 = f2fma(m0, pX[vi], f2fma(m1, pY[vi], f2fma(m2,  pZ[vi], m3)));
            ull t1 = f2fma(m4, pX[vi], f2fma(m5, pY[vi], f2fma(m6,  pZ[vi], m7)));
            ull t2 = f2fma(m8, pX[vi], f2fma(m9, pY[vi], f2fma(m10, pZ[vi], m11)));
            o[vi * 3 + 0] = f2fma(w, t0, o[vi * 3 + 0]);
            o[vi * 3 + 1] = f2fma(w, t1, o[vi * 3 + 1]);
            o[vi * 3 + 2] = f2fma(w, t2, o[vi * 3 + 2]);
        }
    }

    float oa[12], ob[12];
#pragma unroll
    for (int i = 0; i < 12; i++) upk2(o[i], oa[i], ob[i]);

#pragma unroll
    for (int vi = 0; vi < 4; vi++) {
        int v = v0 + vq * 4 + vi;
        int tp = -1;
        if (v == 745) tp = 4; else if (v == 317) tp = 8;
        else if (v == 444) tp = 12; else if (v == 556) tp = 16;
        else if (v == 673) tp = 20;
        if (tp >= 0) {
            int base = vi * 3;
            outJ[((bA)     * 21 + tp) * 3 + 0] = oa[base + 0];
            outJ[((bA)     * 21 + tp) * 3 + 1] = oa[base + 1];
            outJ[((bA)     * 21 + tp) * 3 + 2] = oa[base + 2];
            outJ[((bA + 1) * 21 + tp) * 3 + 0] = ob[base + 0];
            outJ[((bA + 1) * 21 + tp) * 3 + 1] = ob[base + 1];
            outJ[((bA + 1) * 21 + tp) * 3 + 2] = ob[base + 2];
        }
    }

    const int cbase = c0 + vq * 12;
    if (cbase + 12 <= CTOT) {
        float* p0 = &outV[(size_t)bA * CTOT + cbase];
        float* p1 = p0 + CTOT;
#pragma unroll
        for (int q = 0; q < 6; q++) {
            reinterpret_cast<float2*>(p0)[q] = make_float2(oa[q*2], oa[q*2+1]);
            reinterpret_cast<float2*>(p1)[q] = make_float2(ob[q*2], ob[q*2+1]);
        }
    } else if (cbase < CTOT) {
        int nval = CTOT - cbase;
        float* p0 = &outV[(size_t)bA * CTOT + cbase];
        float* p1 = p0 + CTOT;
        for (int q = 0; q < nval; q++) { p0[q] = oa[q]; p1[q] = ob[q]; }
    }
}

// ---------------------------------------------------------------------------
extern "C" void kernel_launch(void* const* d_in, const int* in_sizes, int n_in,
                              void* d_out, int out_size) {
    const float* grmt  = (const float*)d_in[0];
    const float* frmt  = (const float*)d_in[1];
    const float* shape = (const float*)d_in[2];
    const float* trans = (const float*)d_in[3];
    const float* vt    = (const float*)d_in[4];
    const float* sd    = (const float*)d_in[5];
    const float* jreg  = (const float*)d_in[6];
    const float* pd    = (const float*)d_in[7];
    const float* lbs   = (const float*)d_in[8];

    float* out  = (float*)d_out;
    float* outV = out;
    float* outJ = out + (size_t)BB * CTOT;

    static bool attr_done = false;
    if (!attr_done) {
        cudaFuncSetAttribute(k3_gemm, cudaFuncAttributeMaxDynamicSharedMemorySize,
                             SM_K3);
        attr_done = true;
    }

    k0_B<<<dim3((CPAD + 255) / 256, 24), 256>>>(vt, sd, pd);
    k0_A<<<(BB * GK) / 256, 256>>>(shape, frmt);
    k1_jreg<<<NJJ, 128>>>(jreg, vt, sd);
    k2_joints<<<BB / 4, 256>>>(grmt, frmt, shape, trans, outJ);
    k3_gemm<<<dim3(BB / 128, 13), 512, SM_K3>>>();
    k4_epi<<<dim3(BB / 32, 13), 256>>>(lbs, outV, outJ);
}

// round 6
// speedup vs baseline: 2.0287x; 1.3654x over previous
#include <cuda_runtime.h>
#include <cuda_bf16.h>
#include <cstdint>

#define BB    8192
#define NVV   778
#define NJJ   16
#define CTOT  2334
#define CPAD  2496          // 13 * 192
#define GK    192           // padded K (145 feat + pad; bias removed from GEMM)

// ---------------- device scratch (static; no runtime alloc) ----------------
__device__ __align__(16) float          g_V[(size_t)BB * CPAD];      // GEMM out (corrections only)
__device__ __align__(16) __nv_bfloat16  g_A[BB * GK];
__device__ __align__(16) __nv_bfloat16  g_B[CPAD * GK];              // B^T [n][k]
__device__ __align__(16) float g_J0[NJJ * 3];
__device__ __align__(16) float g_JS[NJJ * 3 * 10];
// M'' batch-pair interleaved: [b/2][j][k][parity]
__device__ __align__(16) float g_M[(BB / 2) * NJJ * 12 * 2];

__constant__ int c_par[16] = {0,0,1,2,0,4,5,0,7,8,0,10,11,0,13,14};
__constant__ int c_inv[16] = {0,5,6,7,9,10,11,17,18,19,13,14,15,1,2,3};

typedef unsigned long long ull;

__device__ __forceinline__ ull pk2(float lo, float hi) {
    ull r;
    asm("mov.b64 %0, {%1, %2};" : "=l"(r) : "f"(lo), "f"(hi));
    return r;
}
__device__ __forceinline__ void upk2(ull v, float& lo, float& hi) {
    asm("mov.b64 {%0, %1}, %2;" : "=f"(lo), "=f"(hi) : "l"(v));
}
__device__ __forceinline__ ull f2fma(ull a, ull b, ull c) {
    ull d;
    asm("fma.rn.f32x2 %0, %1, %2, %3;" : "=l"(d) : "l"(a), "l"(b), "l"(c));
    return d;
}

__device__ __forceinline__ void mma16816(float* d, const uint32_t* a,
                                         const uint32_t* b) {
    asm volatile(
        "mma.sync.aligned.m16n8k16.row.col.f32.bf16.bf16.f32 "
        "{%0,%1,%2,%3}, {%4,%5,%6,%7}, {%8,%9}, {%0,%1,%2,%3};"
        : "+f"(d[0]), "+f"(d[1]), "+f"(d[2]), "+f"(d[3])
        : "r"(a[0]), "r"(a[1]), "r"(a[2]), "r"(a[3]), "r"(b[0]), "r"(b[1]));
}

__device__ __forceinline__ uint32_t smem_u32(const void* p) {
    uint32_t a;
    asm("{ .reg .u64 t; cvta.to.shared.u64 t, %1; cvt.u32.u64 %0, t; }"
        : "=r"(a) : "l"(p));
    return a;
}
__device__ __forceinline__ void cpasync16(uint32_t dst, const void* src) {
    asm volatile("cp.async.ca.shared.global [%0], [%1], 16;"
                 :: "r"(dst), "l"(src));
}
#define CP_COMMIT()  asm volatile("cp.async.commit_group;" ::: "memory")
#define CP_WAIT(n)   asm volatile("cp.async.wait_group %0;" :: "n"(n) : "memory")

// ---------------------------------------------------------------------------
// K0: merged prep.  blocks [0,6144): A build; [6144,6384): B build;
//                   [6384,6400): joint-regressor contractions
// ---------------------------------------------------------------------------
__global__ __launch_bounds__(256) void k0_prep(const float* __restrict__ vt,
                                               const float* __restrict__ sd,
                                               const float* __restrict__ pd,
                                               const float* __restrict__ shape,
                                               const float* __restrict__ finger,
                                               const float* __restrict__ jreg) {
    __shared__ float red[33 * 256];
    const int blk = blockIdx.x, tid = threadIdx.x;

    if (blk < 6144) {                       // ---- A: feat bf16 [B x 192]
        int idx = blk * 256 + tid;
        int b = idx / GK, k = idx - b * GK;
        float val = 0.f;
        if (k < 10) val = shape[b * 10 + k];
        else if (k < 145) {
            int q = k - 10;
            val = finger[b * 135 + q];
            if (((q % 9) & 3) == 0) val -= 1.0f;
        }
        g_A[idx] = __float2bfloat16_rn(val);
        return;
    }
    if (blk < 6384) {                       // ---- B^T bf16 [n][k]
        int q = blk - 6144;
        int kg = q / 10, nb = q - kg * 10;
        int n = nb * 256 + tid;
        if (n >= CPAD) return;
        unsigned short hs[8];
#pragma unroll
        for (int i = 0; i < 8; i++) {
            int k = kg * 8 + i;
            float val = 0.f;
            if (n < CTOT) {
                if (k < 10)       val = sd[n * 10 + k];
                else if (k < 145) val = pd[(k - 10) * CTOT + n];
            }
            hs[i] = __bfloat16_as_ushort(__float2bfloat16_rn(val));
        }
        uint4 ph;
        ph.x = hs[0] | ((uint32_t)hs[1] << 16);
        ph.y = hs[2] | ((uint32_t)hs[3] << 16);
        ph.z = hs[4] | ((uint32_t)hs[5] << 16);
        ph.w = hs[6] | ((uint32_t)hs[7] << 16);
        *reinterpret_cast<uint4*>(&g_B[n * GK + kg * 8]) = ph;
        return;
    }
    // ---- joint regressor: one block per joint
    const int j = blk - 6384;
    float acc[33];
#pragma unroll
    for (int o = 0; o < 33; o++) acc[o] = 0.f;
    for (int v = tid; v < NVV; v += 256) {
        float w = jreg[j * NVV + v];
#pragma unroll
        for (int k = 0; k < 3; k++) {
            acc[k] += w * vt[v * 3 + k];
#pragma unroll
            for (int l = 0; l < 10; l++)
                acc[3 + k * 10 + l] += w * sd[(v * 3 + k) * 10 + l];
        }
    }
    for (int o = 0; o < 33; o++) red[o * 256 + tid] = acc[o];
    __syncthreads();
    if (tid < 33) {
        float s = 0.f;
        for (int i = 0; i < 256; i++) s += red[tid * 256 + i];
        if (tid < 3) g_J0[j * 3 + tid] = s;
        else {
            int o = tid - 3;
            int k = o / 10, l = o - k * 10;
            g_JS[(j * 3 + k) * 10 + l] = s;
        }
    }
}

// ---------------------------------------------------------------------------
// K2: joint chain — 4 batches per 256-thread CTA, coalesced frmt staging
// ---------------------------------------------------------------------------
__device__ __forceinline__ void mul4(const float* a, float* d) {
    float t[16];
#pragma unroll
    for (int r = 0; r < 4; r++)
#pragma unroll
        for (int c = 0; c < 4; c++)
            t[r * 4 + c] = a[r * 4 + 0] * d[0 + c] + a[r * 4 + 1] * d[4 + c] +
                           a[r * 4 + 2] * d[8 + c] + a[r * 4 + 3] * d[12 + c];
#pragma unroll
    for (int i = 0; i < 16; i++) d[i] = t[i];
}

__global__ __launch_bounds__(256) void k2_joints(const float* __restrict__ grmt,
                          const float* __restrict__ frmt,
                          const float* __restrict__ shape,
                          const float* __restrict__ trans,
                          float* __restrict__ outJ) {
    __shared__ float sJ[4][16][3];
    __shared__ float sM[4][16][16];
    __shared__ float sF[4][136];
    __shared__ float sg[4][9], st[4][3], ssh[4][10];
    const int tid = threadIdx.x;
    const int bs = tid >> 6;
    const int tl = tid & 63;
    const int b = blockIdx.x * 4 + bs;
    const int b0 = blockIdx.x * 4;

    // coalesced frmt stage: 4 x 135 floats
    for (int i = tid; i < 540; i += 256) {
        int s = i / 135, q = i - s * 135;
        sF[s][q] = frmt[(b0 + s) * 135 + q];
    }
    if (tl < 9)  sg[bs][tl]  = grmt[b * 9 + tl];
    if (tl < 3)  st[bs][tl]  = trans[b * 3 + tl];
    if (tl < 10) ssh[bs][tl] = shape[b * 10 + tl];
    __syncthreads();

    if (tl < 48) {
        int j = tl / 3, k = tl - j * 3;
        float a = g_J0[j * 3 + k];
#pragma unroll
        for (int l = 0; l < 10; l++) a += ssh[bs][l] * g_JS[(j * 3 + k) * 10 + l];
        sJ[bs][j][k] = a;
    }
    __syncthreads();

    if (tl < 16) {
        int j = tl;
        float R[9];
        if (j == 0) {
            R[0]=1;R[1]=0;R[2]=0;R[3]=0;R[4]=1;R[5]=0;R[6]=0;R[7]=0;R[8]=1;
        } else {
#pragma unroll
            for (int i = 0; i < 9; i++) R[i] = sF[bs][(j - 1) * 9 + i];
        }
        float t0 = sJ[bs][j][0], t1 = sJ[bs][j][1], t2 = sJ[bs][j][2];
        if (j > 0) {
            int p = c_par[j];
            t0 -= sJ[bs][p][0]; t1 -= sJ[bs][p][1]; t2 -= sJ[bs][p][2];
        }
        float* m = sM[bs][j];
        m[0]=R[0]; m[1]=R[1]; m[2]=R[2];  m[3]=t0;
        m[4]=R[3]; m[5]=R[4]; m[6]=R[5];  m[7]=t1;
        m[8]=R[6]; m[9]=R[7]; m[10]=R[8]; m[11]=t2;
        m[12]=0.f; m[13]=0.f; m[14]=0.f;  m[15]=1.f;
    }
    __syncthreads();

    if (tl < 5) {
        int j = 1 + 3 * tl;
        mul4(sM[bs][0], sM[bs][j]);
        mul4(sM[bs][j], sM[bs][j + 1]);
        mul4(sM[bs][j + 1], sM[bs][j + 2]);
    }
    __syncthreads();

    if (tl < 16) {
        int j = tl;
        const float* m = sM[bs][j];
        float jt0 = m[3], jt1 = m[7], jt2 = m[11];
        float J0 = sJ[bs][j][0], J1 = sJ[bs][j][1], J2 = sJ[bs][j][2];
        float tc0 = jt0 - (m[0] * J0 + m[1] * J1 + m[2]  * J2);
        float tc1 = jt1 - (m[4] * J0 + m[5] * J1 + m[6]  * J2);
        float tc2 = jt2 - (m[8] * J0 + m[9] * J1 + m[10] * J2);
        float* o = &g_M[(((b >> 1) * 16 + j) * 12) * 2 + (b & 1)];
        float row[12];
        int jp = c_inv[j];
#pragma unroll
        for (int r = 0; r < 3; r++) {
            float a = sg[bs][r * 3 + 0], bb = sg[bs][r * 3 + 1], cc = sg[bs][r * 3 + 2];
            row[r * 4 + 0] = a * m[0] + bb * m[4] + cc * m[8];
            row[r * 4 + 1] = a * m[1] + bb * m[5] + cc * m[9];
            row[r * 4 + 2] = a * m[2] + bb * m[6] + cc * m[10];
            row[r * 4 + 3] = a * tc0  + bb * tc1  + cc * tc2 + st[bs][r];
            outJ[(b * 21 + jp) * 3 + r] = a * jt0 + bb * jt1 + cc * jt2 + st[bs][r];
        }
#pragma unroll
        for (int k = 0; k < 12; k++) o[k * 2] = row[k];
    }
}

// ---------------------------------------------------------------------------
// K3: single-bf16 mma.sync GEMM with cp.async 2-stage pipeline -> g_V
//   CTA: 512 thr, tile 128(b) x 192(n), K=192 in 3 chunks of 64
//   Stage: A 128x144B @0, B 192x144B @18432; stage size 46080, x2 = 92160
// ---------------------------------------------------------------------------
#define STG_SZ  46080
#define SM_K3   92160

__global__ __launch_bounds__(512, 1) void k3_gemm() {
    extern __shared__ __align__(16) char smem[];
    const uint32_t sbase = smem_u32(smem);
    const int tid = threadIdx.x;
    const int wid = tid >> 5, lane = tid & 31;
    const int wm = wid & 1, wn = wid >> 1;      // 2 m-warps x 8 n-warps
    const int gid = lane >> 2, tig = lane & 3;
    const int b0 = blockIdx.x * 128;
    const int t  = blockIdx.y;

    auto stage_chunk = [&](int s, int ch) {
        const uint32_t stg = sbase + s * STG_SZ;
        for (int i = tid; i < 2560; i += 512) {
            if (i < 1024) {
                int r = i >> 3, q = i & 7;
                cpasync16(stg + r * 144 + q * 16,
                          &g_A[(b0 + r) * GK + ch * 64 + q * 8]);
            } else {
                int i2 = i - 1024;
                int r = i2 >> 3, q = i2 & 7;
                cpasync16(stg + 18432 + r * 144 + q * 16,
                          &g_B[(t * 192 + r) * GK + ch * 64 + q * 8]);
            }
        }
    };

    float d[4][3][4];
#pragma unroll
    for (int mt = 0; mt < 4; mt++)
#pragma unroll
        for (int nt = 0; nt < 3; nt++)
#pragma unroll
            for (int q = 0; q < 4; q++) d[mt][nt][q] = 0.f;

    stage_chunk(0, 0); CP_COMMIT();
    stage_chunk(1, 1); CP_COMMIT();

    auto mma_chunk = [&](int s) {
        const char* stg = smem + s * STG_SZ;
#pragma unroll
        for (int ks = 0; ks < 4; ks++) {
            const int kb = ks * 32 + tig * 4;
            uint32_t ah[4][4];
#pragma unroll
            for (int mt = 0; mt < 4; mt++) {
                int r0 = wm * 64 + mt * 16 + gid;
                const char* ph = stg + r0 * 144 + kb;
                ah[mt][0] = *(const uint32_t*)(ph);
                ah[mt][1] = *(const uint32_t*)(ph + 8 * 144);
                ah[mt][2] = *(const uint32_t*)(ph + 16);
                ah[mt][3] = *(const uint32_t*)(ph + 8 * 144 + 16);
            }
            uint32_t bh[3][2];
#pragma unroll
            for (int nt = 0; nt < 3; nt++) {
                int n0 = wn * 24 + nt * 8 + gid;
                const char* ph = stg + 18432 + n0 * 144 + kb;
                bh[nt][0] = *(const uint32_t*)(ph);
                bh[nt][1] = *(const uint32_t*)(ph + 16);
            }
#pragma unroll
            for (int mt = 0; mt < 4; mt++)
#pragma unroll
                for (int nt = 0; nt < 3; nt++)
                    mma16816(d[mt][nt], ah[mt], bh[nt]);
        }
    };

    CP_WAIT(1); __syncthreads();
    mma_chunk(0);
    __syncthreads();
    stage_chunk(0, 2); CP_COMMIT();
    CP_WAIT(1); __syncthreads();
    mma_chunk(1);
    CP_WAIT(0); __syncthreads();
    mma_chunk(0);

#pragma unroll
    for (int mt = 0; mt < 4; mt++) {
        int r0 = b0 + wm * 64 + mt * 16 + gid;
#pragma unroll
        for (int nt = 0; nt < 3; nt++) {
            int c = t * 192 + wn * 24 + nt * 8 + tig * 2;
            *reinterpret_cast<float2*>(&g_V[(size_t)r0 * CPAD + c]) =
                make_float2(d[mt][nt][0], d[mt][nt][1]);
            *reinterpret_cast<float2*>(&g_V[(size_t)(r0 + 8) * CPAD + c]) =
                make_float2(d[mt][nt][2], d[mt][nt][3]);
        }
    }
}

// ---------------------------------------------------------------------------
// K4: LBS epilogue, f32x2 over batch pairs. 2 verts/thread, 2-pair loop.
//   CTA: 256 thr, tile 32 batch x 64 verts. fp32 template bias added here.
// ---------------------------------------------------------------------------
__global__ __launch_bounds__(256, 3) void k4_epi(const float* __restrict__ lbs,
                                                 const float* __restrict__ vt,
                                                 float* __restrict__ outV,
                                                 float* __restrict__ outJ) {
    __shared__ __align__(16) float sMmP[16 * 392];
    __shared__ __align__(16) float sW2[16 * 64 * 2];
    const int tid = threadIdx.x;
    const int b0 = blockIdx.x * 32;
    const int v0 = blockIdx.y * 64;
    const int c0 = v0 * 3;

    {
        const float4* src = reinterpret_cast<const float4*>(
            &g_M[(size_t)(b0 / 2) * 384]);
        for (int i = tid; i < 1536; i += 256) {
            int pr = i / 96, q = i - pr * 96;
            *reinterpret_cast<float4*>(&sMmP[pr * 392 + q * 4]) = src[i];
        }
    }
    for (int i = tid; i < 1024; i += 256) {
        int v = i >> 4, j = i & 15;
        float w = (v0 + v < NVV) ? lbs[(v0 + v) * 16 + j] : 0.f;
        sW2[(j * 64 + v) * 2]     = w;
        sW2[(j * 64 + v) * 2 + 1] = w;
    }
    __syncthreads();

    const int vq = tid & 31;      // vert pair group: verts vq*2, vq*2+1
    const int pq = tid >> 5;      // 0..7
    const int cbase = c0 + vq * 6;
    const bool cok = (cbase + 6 <= CTOT);

    // fp32 template bias for this thread's 6 columns
    float bias[6];
#pragma unroll
    for (int q = 0; q < 6; q++)
        bias[q] = (cbase + q < CTOT) ? vt[cbase + q] : 0.f;

#pragma unroll
    for (int u = 0; u < 2; u++) {
        const int p  = pq * 2 + u;     // pair 0..15
        const int bA = b0 + p * 2;

        float va[6], vb[6];
        {
            const float* p0 = &g_V[(size_t)bA * CPAD + cbase];
            const float* p1 = p0 + CPAD;
#pragma unroll
            for (int q = 0; q < 3; q++) {
                float2 x0 = reinterpret_cast<const float2*>(p0)[q];
                float2 x1 = reinterpret_cast<const float2*>(p1)[q];
                va[q*2+0] = x0.x + bias[q*2+0]; va[q*2+1] = x0.y + bias[q*2+1];
                vb[q*2+0] = x1.x + bias[q*2+0]; vb[q*2+1] = x1.y + bias[q*2+1];
            }
        }
        ull pX[2], pY[2], pZ[2];
#pragma unroll
        for (int vi = 0; vi < 2; vi++) {
            pX[vi] = pk2(va[vi * 3 + 0], vb[vi * 3 + 0]);
            pY[vi] = pk2(va[vi * 3 + 1], vb[vi * 3 + 1]);
            pZ[vi] = pk2(va[vi * 3 + 2], vb[vi * 3 + 2]);
        }

        ull o[6];
#pragma unroll
        for (int i = 0; i < 6; i++) o[i] = 0ull;

#pragma unroll 4
        for (int j = 0; j < 16; j++) {
            const ull* mp = reinterpret_cast<const ull*>(&sMmP[p * 392 + j * 24]);
            const ull* wp = reinterpret_cast<const ull*>(&sW2[(j * 64 + vq * 2) * 2]);
            ull m0 = mp[0], m1 = mp[1], m2 = mp[2],  m3 = mp[3];
            ull m4 = mp[4], m5 = mp[5], m6 = mp[6],  m7 = mp[7];
            ull m8 = mp[8], m9 = mp[9], m10 = mp[10], m11 = mp[11];
#pragma unroll
            for (int vi = 0; vi < 2; vi++) {
                ull w = wp[vi];
                ull t0 = f2fma(m0, pX[vi], f2fma(m1, pY[vi], f2fma(m2,  pZ[vi], m3)));
                ull t1 = f2fma(m4, pX[vi], f2fma(m5, pY[vi], f2fma(m6,  pZ[vi], m7)));
                ull t2 = f2fma(m8, pX[vi], f2fma(m9, pY[vi], f2fma(m10, pZ[vi], m11)));
                o[vi * 3 + 0] = f2fma(w, t0, o[vi * 3 + 0]);
                o[vi * 3 + 1] = f2fma(w, t1, o[vi * 3 + 1]);
                o[vi * 3 + 2] = f2fma(w, t2, o[vi * 3 + 2]);
            }
        }

        float oa[6], ob[6];
#pragma unroll
        for (int i = 0; i < 6; i++) upk2(o[i], oa[i], ob[i]);

#pragma unroll
        for (int vi = 0; vi < 2; vi++) {
            int v = v0 + vq * 2 + vi;
            int tp = -1;
            if (v == 745) tp = 4; else if (v == 317) tp = 8;
            else if (v == 444) tp = 12; else if (v == 556) tp = 16;
            else if (v == 673) tp = 20;
            if (tp >= 0) {
                int base = vi * 3;
                outJ[((bA)     * 21 + tp) * 3 + 0] = oa[base + 0];
                outJ[((bA)     * 21 + tp) * 3 + 1] = oa[base + 1];
                outJ[((bA)     * 21 + tp) * 3 + 2] = oa[base + 2];
                outJ[((bA + 1) * 21 + tp) * 3 + 0] = ob[base + 0];
                outJ[((bA + 1) * 21 + tp) * 3 + 1] = ob[base + 1];
                outJ[((bA + 1) * 21 + tp) * 3 + 2] = ob[base + 2];
            }
        }

        if (cok) {
            float* p0 = &outV[(size_t)bA * CTOT + cbase];
            float* p1 = p0 + CTOT;
#pragma unroll
            for (int q = 0; q < 3; q++) {
                reinterpret_cast<float2*>(p0)[q] = make_float2(oa[q*2], oa[q*2+1]);
                reinterpret_cast<float2*>(p1)[q] = make_float2(ob[q*2], ob[q*2+1]);
            }
        } else if (cbase < CTOT) {
            int nval = CTOT - cbase;
            float* p0 = &outV[(size_t)bA * CTOT + cbase];
            float* p1 = p0 + CTOT;
            for (int q = 0; q < nval; q++) { p0[q] = oa[q]; p1[q] = ob[q]; }
        }
    }
}

// ---------------------------------------------------------------------------
extern "C" void kernel_launch(void* const* d_in, const int* in_sizes, int n_in,
                              void* d_out, int out_size) {
    const float* grmt  = (const float*)d_in[0];
    const float* frmt  = (const float*)d_in[1];
    const float* shape = (const float*)d_in[2];
    const float* trans = (const float*)d_in[3];
    const float* vt    = (const float*)d_in[4];
    const float* sd    = (const float*)d_in[5];
    const float* jreg  = (const float*)d_in[6];
    const float* pd    = (const float*)d_in[7];
    const float* lbs   = (const float*)d_in[8];

    float* out  = (float*)d_out;
    float* outV = out;
    float* outJ = out + (size_t)BB * CTOT;

    static bool attr_done = false;
    if (!attr_done) {
        cudaFuncSetAttribute(k3_gemm, cudaFuncAttributeMaxDynamicSharedMemorySize,
                             SM_K3);
        attr_done = true;
    }

    k0_prep<<<6400, 256>>>(vt, sd, pd, shape, frmt, jreg);
    k2_joints<<<BB / 4, 256>>>(grmt, frmt, shape, trans, outJ);
    k3_gemm<<<dim3(BB / 128, 13), 512, SM_K3>>>();
    k4_epi<<<dim3(BB / 32, 13), 256>>>(lbs, vt, outV, outJ);
}